// round 3
// baseline (speedup 1.0000x reference)
#include <cuda_runtime.h>
#include <float.h>

// Problem constants
#define B_   16
#define P_   4096
#define T_   1024
#define G_   64                 // 64x64 cells of size 8.0 covering [0,512)
#define NC_  (G_*G_)
#define CAP_ 16
#define RADIUS_ 2.5f
#define SENT_ 0xFFFFFFFFFFFFFFFFull

#define NB_   148               // <= SM count -> all blocks co-resident -> grid barrier safe
#define NT_   1024
#define NTOT_ (NB_*NT_)         // 151552 >= every phase size -> each loop runs <=1x per thread

// Scratch (device globals: no allocation allowed)
__device__ int                g_cnt [B_*NC_];
__device__ float4             g_cell[B_*NC_*CAP_];
__device__ int                g_ovfn[B_];
__device__ float4             g_ovf [B_*T_];
__device__ unsigned long long g_best[B_*T_];     // packed (dsq_bits<<32)|p ; min => min d then min p
__device__ float              g_mind[B_*P_];
__device__ int                g_corr[B_*P_];
__device__ double             g_pobj[NB_];
__device__ double             g_preg[NB_];
__device__ volatile unsigned long long g_bar;    // monotonic ticket barrier (never reset)

// Grid-wide barrier: monotonic counter; safe across graph replays.
__device__ __forceinline__ void gbar() {
    __syncthreads();
    if (threadIdx.x == 0) {
        __threadfence();
        unsigned long long my = atomicAdd((unsigned long long*)&g_bar, 1ull);
        unsigned long long tgt = (my / NB_ + 1ull) * NB_;
        while (g_bar < tgt) __nanosleep(32);
    }
    __syncthreads();
}

__device__ __forceinline__ void consider(float4 v, float cls, float x, float y,
                                         int p, unsigned long long* bestBase,
                                         float& mind) {
    float dx = x - v.y, dy = y - v.z;
    float dsq = dx*dx + dy*dy;
    mind = fminf(mind, dsq);
    float d = sqrtf(dsq + 1e-12f);
    if (d <= RADIUS_ && cls == v.x) {
        int t = __float_as_int(v.w);
        unsigned long long key = ((unsigned long long)__float_as_uint(dsq) << 32)
                               | (unsigned int)p;
        atomicMin(bestBase + t, key);
    }
}

__global__ void __launch_bounds__(NT_, 1)
fused_kernel(const float* __restrict__ pred, const float* __restrict__ gt,
             float* __restrict__ out) {
    const int tid = threadIdx.x;
    const int i0  = blockIdx.x * NT_ + tid;

    // ---- Phase 0: init scratch (each array <= NTOT_ elements) ------------
    if (i0 < B_*NC_) g_cnt[i0]  = 0;
    if (i0 < B_*P_)  g_corr[i0] = 0;
    if (i0 < B_*T_)  g_best[i0] = SENT_;
    if (i0 < B_)     g_ovfn[i0] = 0;
    gbar();

    // ---- Phase 1: bin targets into spatial hash --------------------------
    if (i0 < B_*T_) {
        int b = i0 >> 10;
        int t = i0 & (T_ - 1);
        const float* g = gt + (size_t)i0 * 3;
        float tc = g[0], tx = g[1], ty = g[2];
        int cx = (int)(tx * 0.125f); cx = min(max(cx, 0), G_-1);
        int cy = (int)(ty * 0.125f); cy = min(max(cy, 0), G_-1);
        int c = b*NC_ + cy*G_ + cx;
        int pos = atomicAdd(&g_cnt[c], 1);
        float4 v = make_float4(tc, tx, ty, __int_as_float(t));
        if (pos < CAP_) {
            g_cell[c*CAP_ + pos] = v;
        } else {
            int j = atomicAdd(&g_ovfn[b], 1);
            g_ovf[b*T_ + j] = v;
        }
    }
    gbar();

    // ---- Phase 2: per-pred 3x3 neighborhood scan (front-batched loads) ---
    if (i0 < B_*P_) {
        int b = i0 >> 12;
        int p = i0 & (P_ - 1);
        float4 pr = __ldg(reinterpret_cast<const float4*>(pred) + i0);  // {cls,x,y,conf}
        float cls = pr.x, x = pr.y, y = pr.z;

        int cx = (int)(x * 0.125f); cx = min(max(cx, 0), G_-1);
        int cy = (int)(y * 0.125f); cy = min(max(cy, 0), G_-1);

        // Gather all 9 cell counts up front (independent loads -> MLP)
        int cidx[9];
        int ccnt[9];
        #pragma unroll
        for (int k = 0; k < 9; k++) {
            int yy = cy + (k / 3) - 1;
            int xx = cx + (k % 3) - 1;
            bool ok = (yy >= 0) & (yy < G_) & (xx >= 0) & (xx < G_);
            int c = b*NC_ + yy*G_ + xx;
            cidx[k] = c;
            ccnt[k] = ok ? __ldcg(&g_cnt[c]) : 0;
        }

        unsigned long long* bestBase = g_best + b*T_;
        float mind = FLT_MAX;

        #pragma unroll
        for (int k = 0; k < 9; k++) {
            int cnt = min(ccnt[k], CAP_);
            const float4* slot = &g_cell[cidx[k]*CAP_];
            for (int j = 0; j < cnt; j++)
                consider(__ldcg(slot + j), cls, x, y, p, bestBase, mind);
        }
        int novf = __ldcg(&g_ovfn[b]);     // normally 0
        for (int j = 0; j < novf; j++)
            consider(__ldcg(&g_ovf[b*T_ + j]), cls, x, y, p, bestBase, mind);

        g_mind[i0] = mind;
    }
    gbar();

    // ---- Phase 3: scatter correctness flags ------------------------------
    if (i0 < B_*T_) {
        unsigned long long v = __ldcg(&g_best[i0]);
        if (v != SENT_) {
            int b = i0 >> 10;
            int p = (int)(v & 0xFFFFFFFFull);
            g_corr[b*P_ + p] = 1;          // benign race: all write 1
        }
    }
    gbar();

    // ---- Phase 4: parallel deterministic reduction -----------------------
    __shared__ double s_obj[NT_];
    __shared__ double s_reg[NT_];
    double so = 0.0, sr = 0.0;
    if (i0 < B_*P_) {
        float conf = __ldg(&pred[4*i0 + 3]);
        int   c    = __ldcg(&g_corr[i0]);
        float cf   = (float)c;
        so = (double)(fmaxf(conf, 0.0f) - conf*cf + log1pf(expf(-fabsf(conf))));
        float rt = 1.0f;
        if (c) {
            float d = sqrtf(__ldcg(&g_mind[i0]) + 1e-12f);
            float s = 1.0f / (1.0f + expf(-(RADIUS_ - d)));
            rt = 1.0f - s;
        }
        sr = (double)rt;
    }
    s_obj[tid] = so; s_reg[tid] = sr;
    __syncthreads();
    for (int off = NT_/2; off > 0; off >>= 1) {
        if (tid < off) { s_obj[tid] += s_obj[tid+off]; s_reg[tid] += s_reg[tid+off]; }
        __syncthreads();
    }
    if (tid == 0) { g_pobj[blockIdx.x] = s_obj[0]; g_preg[blockIdx.x] = s_reg[0]; }
    gbar();

    // ---- Phase 5: block 0 combines 148 partials (fixed tree) -------------
    if (blockIdx.x == 0) {
        double a = 0.0, r = 0.0;
        if (tid < NB_) { a = __ldcg(&g_pobj[tid]); r = __ldcg(&g_preg[tid]); }
        s_obj[tid] = a; s_reg[tid] = r;
        __syncthreads();
        for (int off = NT_/2; off > 0; off >>= 1) {
            if (tid < off) { s_obj[tid] += s_obj[tid+off]; s_reg[tid] += s_reg[tid+off]; }
            __syncthreads();
        }
        if (tid == 0) {
            out[0] = (float)(s_obj[0] / 65536.0);   // obj_loss
            out[1] = (float)(s_reg[0] / 65536.0);   // reg_loss
        }
    }
}

extern "C" void kernel_launch(void* const* d_in, const int* in_sizes, int n_in,
                              void* d_out, int out_size) {
    const float* pred = (const float*)d_in[0];
    const float* gt   = (const float*)d_in[1];
    if (n_in >= 2 && in_sizes[0] == B_*T_*3) {   // defensive input-order check
        const float* tmp = pred; pred = gt; gt = tmp;
    }
    (void)out_size;
    fused_kernel<<<NB_, NT_>>>(pred, gt, (float*)d_out);
}

// round 4
// speedup vs baseline: 1.3633x; 1.3633x over previous
#include <cuda_runtime.h>
#include <float.h>

// Problem constants
#define B_   16
#define P_   4096
#define T_   1024
#define G_   64                 // 64x64 cells of size 8.0 covering [0,512)
#define NC_  (G_*G_)
#define CAP_ 16
#define RADIUS_ 2.5f

#define NB_   148               // <= SM count -> all blocks co-resident -> grid barrier safe
#define NT_   256               // 256 measured faster than 1024 (cheaper bar, less skew)
#define NTOT_ (NB_*NT_)         // 37888

#define SCALE_ 17179869184.0    // 2^34 fixed-point scale (sum < 2^53, exact in int64)

// Scratch (device globals; statically zero-initialized at module load).
// Invariant: every launch leaves all state "empty" for the next replay.
__device__ int                g_cnt [B_*NC_];   // cleared in phase C
__device__ float4             g_cell[B_*NC_*CAP_];  // guarded by g_cnt
__device__ int                g_ovfn[B_];           // cleared in phase C
__device__ float4             g_ovf [B_*T_];        // guarded by g_ovfn
__device__ unsigned long long g_best[B_*T_];    // atomicMax of ~((dsq<<32)|p); 0 = empty; cleared in C
__device__ float              g_mind[B_*P_];    // fully overwritten each launch in phase B
__device__ unsigned long long g_claim[B_*P_];   // epoch tags; monotonic, never cleared
__device__ unsigned long long g_acc_obj;        // fixed-point Σ bce_base        (reset by last block)
__device__ unsigned long long g_acc_cobj;       // fixed-point Σ_{correct} conf  (reset by last block)
__device__ unsigned long long g_acc_creg;       // fixed-point Σ_{correct} sigm  (reset by last block)
__device__ unsigned long long g_bar;            // monotonic ticket barrier
__device__ unsigned int       g_done;           // monotonic last-block counter

// Grid barrier; returns the (launch-unique, monotonic) release ticket.
__device__ __forceinline__ unsigned long long gbar() {
    __shared__ unsigned long long sh_tgt;
    __syncthreads();
    if (threadIdx.x == 0) {
        __threadfence();
        unsigned long long my  = atomicAdd(&g_bar, 1ull);
        unsigned long long tgt = (my / NB_ + 1ull) * NB_;
        while (*((volatile unsigned long long*)&g_bar) < tgt) __nanosleep(32);
        sh_tgt = tgt;
    }
    __syncthreads();
    return sh_tgt;
}

__device__ __forceinline__ long long wred(long long v) {
    #pragma unroll
    for (int o = 16; o; o >>= 1) v += __shfl_down_sync(0xFFFFFFFFu, v, o);
    return v;
}

__device__ __forceinline__ void consider(float4 v, float cls, float x, float y,
                                         int p, unsigned long long* bestBase,
                                         float& mind) {
    float dx = x - v.y, dy = y - v.z;
    float dsq = dx*dx + dy*dy;
    mind = fminf(mind, dsq);
    float d = sqrtf(dsq + 1e-12f);
    if (d <= RADIUS_ && cls == v.x) {
        int t = __float_as_int(v.w);
        // min over (dsq, p) lexicographic == max over bitwise-NOT; 0 stays "empty"
        unsigned long long key = ~(((unsigned long long)__float_as_uint(dsq) << 32)
                                   | (unsigned int)p);
        atomicMax(bestBase + t, key);
    }
}

__global__ void __launch_bounds__(NT_, 1)
fused_kernel(const float* __restrict__ pred, const float* __restrict__ gt,
             float* __restrict__ out) {
    const int tid = threadIdx.x;
    const int i0  = blockIdx.x * NT_ + tid;
    const int lane = tid & 31;
    const float4* __restrict__ pred4 = reinterpret_cast<const float4*>(pred);

    // ---- Phase A: bin targets + base obj sum (pred-only, overlapped) -----
    long long accO = 0;
    for (int i = i0; i < B_*P_; i += NTOT_) {
        float4 pr = __ldg(pred4 + i);                 // {cls,x,y,conf}
        float c = pr.w;
        float bce0 = fmaxf(c, 0.0f) + log1pf(expf(-fabsf(c)));  // BCE with target 0
        accO += (long long)((double)bce0 * SCALE_);

        if (i < B_*T_) {                              // bin target i
            int b = i >> 10;
            int t = i & (T_ - 1);
            const float* g = gt + (size_t)i * 3;
            float tc = g[0], tx = g[1], ty = g[2];
            int cx = (int)(tx * 0.125f); cx = min(max(cx, 0), G_-1);
            int cy = (int)(ty * 0.125f); cy = min(max(cy, 0), G_-1);
            int cidx = b*NC_ + cy*G_ + cx;
            int pos = atomicAdd(&g_cnt[cidx], 1);
            float4 v = make_float4(tc, tx, ty, __int_as_float(t));
            if (pos < CAP_) {
                g_cell[cidx*CAP_ + pos] = v;
            } else {
                int j = atomicAdd(&g_ovfn[b], 1);
                g_ovf[b*T_ + j] = v;
            }
        }
    }
    accO = wred(accO);
    if (lane == 0) atomicAdd(&g_acc_obj, (unsigned long long)accO);

    gbar();

    // ---- Phase B: per-pred 3x3 neighborhood scan --------------------------
    for (int i = i0; i < B_*P_; i += NTOT_) {
        int b = i >> 12;
        int p = i & (P_ - 1);
        float4 pr = __ldg(pred4 + i);
        float cls = pr.x, x = pr.y, y = pr.z;

        int cx = (int)(x * 0.125f); cx = min(max(cx, 0), G_-1);
        int cy = (int)(y * 0.125f); cy = min(max(cy, 0), G_-1);

        int cidx[9]; int ccnt[9];
        #pragma unroll
        for (int k = 0; k < 9; k++) {                 // front-batched count loads
            int yy = cy + (k / 3) - 1;
            int xx = cx + (k % 3) - 1;
            bool ok = (yy >= 0) & (yy < G_) & (xx >= 0) & (xx < G_);
            int c = b*NC_ + yy*G_ + xx;
            cidx[k] = c;
            ccnt[k] = ok ? __ldcg(&g_cnt[c]) : 0;
        }

        unsigned long long* bestBase = g_best + b*T_;
        float mind = FLT_MAX;
        #pragma unroll
        for (int k = 0; k < 9; k++) {
            int cnt = min(ccnt[k], CAP_);
            const float4* slot = &g_cell[cidx[k]*CAP_];
            for (int j = 0; j < cnt; j++)
                consider(__ldcg(slot + j), cls, x, y, p, bestBase, mind);
        }
        int novf = __ldcg(&g_ovfn[b]);                // normally 0
        for (int j = 0; j < novf; j++)
            consider(__ldcg(&g_ovf[b*T_ + j]), cls, x, y, p, bestBase, mind);

        g_mind[i] = mind;
    }

    unsigned long long epoch = gbar();                // launch-unique, > 0

    // ---- Phase C: exactly-once corrections + cleanup + finalize ----------
    long long accCO = 0, accCR = 0;
    for (int i = i0; i < B_*P_; i += NTOT_) {
        g_cnt[i] = 0;                                 // B_*NC_ == B_*P_
        if (i < B_*T_) {
            unsigned long long v = __ldcg(&g_best[i]);
            g_best[i] = 0;                            // reset for next launch
            if (v) {
                unsigned long long vi = ~v;
                int p  = (int)(vi & 0xFFFFFFFFull);
                int b  = i >> 10;
                int pi = b*P_ + p;
                if (atomicExch(&g_claim[pi], epoch) != epoch) {   // exactly-once owner
                    float conf = __ldg(&pred[4*pi + 3]);
                    float dmin = __ldcg(&g_mind[pi]);
                    float d = sqrtf(dmin + 1e-12f);
                    float s = 1.0f / (1.0f + expf(-(RADIUS_ - d)));
                    accCO += (long long)((double)conf * SCALE_);
                    accCR += (long long)((double)s    * SCALE_);
                }
            }
        }
        if (i < B_) g_ovfn[i] = 0;
    }
    accCO = wred(accCO);
    accCR = wred(accCR);
    if (lane == 0) {
        atomicAdd(&g_acc_cobj, (unsigned long long)accCO);
        atomicAdd(&g_acc_creg, (unsigned long long)accCR);
    }

    // Last-block finalization (no grid barrier needed)
    __syncthreads();
    if (tid == 0) {
        __threadfence();
        unsigned int t = atomicAdd(&g_done, 1u);
        if ((t % NB_) == (NB_ - 1u)) {
            long long o  = (long long)atomicAdd(&g_acc_obj,  0ull);
            long long co = (long long)atomicAdd(&g_acc_cobj, 0ull);
            long long cr = (long long)atomicAdd(&g_acc_creg, 0ull);
            double inv = 1.0 / (SCALE_ * 65536.0);
            out[0] = (float)(((double)o - (double)co) * inv);   // obj_loss
            out[1] = (float)(1.0 - (double)cr * inv);           // reg_loss
            atomicExch(&g_acc_obj,  0ull);                      // reset for next replay
            atomicExch(&g_acc_cobj, 0ull);
            atomicExch(&g_acc_creg, 0ull);
        }
    }
}

extern "C" void kernel_launch(void* const* d_in, const int* in_sizes, int n_in,
                              void* d_out, int out_size) {
    const float* pred = (const float*)d_in[0];
    const float* gt   = (const float*)d_in[1];
    if (n_in >= 2 && in_sizes[0] == B_*T_*3) {   // defensive input-order check
        const float* tmp = pred; pred = gt; gt = tmp;
    }
    (void)out_size;
    fused_kernel<<<NB_, NT_>>>(pred, gt, (float*)d_out);
}

// round 5
// speedup vs baseline: 1.7315x; 1.2700x over previous
#include <cuda_runtime.h>
#include <float.h>

// Problem constants
#define B_   16
#define P_   4096
#define T_   1024
#define G_   64                 // 64x64 cells of size 8.0 covering [0,512)
#define NC_  (G_*G_)
#define CAP_ 16
#define RADIUS_ 2.5f

#define NB_   288               // 2 blocks/SM on >=148 SMs -> co-resident -> barrier safe
#define NT_   256
#define NTOT_ (NB_*NT_)         // 73728 > 65536 -> every phase is ONE iteration per thread

#define SCALE_ 17179869184.0    // 2^34 fixed-point scale (sums < 2^53, exact in int64)

// Scratch (device globals; statically zero-initialized at module load).
// Invariant: every launch leaves all state "empty" for the next replay.
__device__ int                g_cnt [B_*NC_];       // cleared in phase C
__device__ float4             g_cell[B_*NC_*CAP_];  // guarded by g_cnt
__device__ int                g_ovfn[B_];           // cleared in phase C
__device__ float4             g_ovf [B_*T_];        // guarded by g_ovfn
__device__ unsigned long long g_best[B_*T_];   // atomicMax of ~((dsq<<32)|p); 0=empty; cleared in C
__device__ float              g_mind[B_*P_];   // fully overwritten each launch in phase B
__device__ unsigned long long g_claim[B_*P_];  // epoch tags; monotonic, never cleared
__device__ unsigned long long g_acc_obj;       // fixed-point Σ bce_base        (reset by last block)
__device__ unsigned long long g_acc_cobj;      // fixed-point Σ_{correct} conf  (reset by last block)
__device__ unsigned long long g_acc_creg;      // fixed-point Σ_{correct} sigm  (reset by last block)
__device__ unsigned long long g_bar;           // monotonic ticket barrier
__device__ unsigned int       g_done;          // monotonic last-block counter

// Grid barrier; returns the (launch-unique, monotonic) release ticket.
__device__ __forceinline__ unsigned long long gbar() {
    __shared__ unsigned long long sh_tgt;
    __syncthreads();
    if (threadIdx.x == 0) {
        __threadfence();
        unsigned long long my  = atomicAdd(&g_bar, 1ull);
        unsigned long long tgt = (my / NB_ + 1ull) * NB_;
        while (*((volatile unsigned long long*)&g_bar) < tgt) __nanosleep(32);
        sh_tgt = tgt;
    }
    __syncthreads();
    return sh_tgt;
}

__device__ __forceinline__ long long wred(long long v) {
    #pragma unroll
    for (int o = 16; o; o >>= 1) v += __shfl_down_sync(0xFFFFFFFFu, v, o);
    return v;
}

__device__ __forceinline__ void consider(float4 v, float cls, float x, float y,
                                         int p, unsigned long long* bestBase,
                                         float& mind) {
    float dx = x - v.y, dy = y - v.z;
    float dsq = dx*dx + dy*dy;
    mind = fminf(mind, dsq);
    float d = sqrtf(dsq + 1e-12f);
    if (d <= RADIUS_ && cls == v.x) {
        int t = __float_as_int(v.w);
        // min over (dsq, p) lexicographic == max over bitwise-NOT; 0 stays "empty"
        unsigned long long key = ~(((unsigned long long)__float_as_uint(dsq) << 32)
                                   | (unsigned int)p);
        atomicMax(bestBase + t, key);
    }
}

__global__ void __launch_bounds__(NT_, 2)
fused_kernel(const float* __restrict__ pred, const float* __restrict__ gt,
             float* __restrict__ out) {
    const int tid  = threadIdx.x;
    const int i0   = blockIdx.x * NT_ + tid;
    const int lane = tid & 31;
    const float4* __restrict__ pred4 = reinterpret_cast<const float4*>(pred);

    // ---- Phase A: bin targets + base obj sum (single pass) ---------------
    long long accO = 0;
    float4 myPred = make_float4(0.f, 0.f, 0.f, 0.f);
    if (i0 < B_*P_) {
        myPred = __ldg(pred4 + i0);                   // {cls,x,y,conf} — reused in phase B
        float c = myPred.w;
        float bce0 = fmaxf(c, 0.0f) + log1pf(expf(-fabsf(c)));  // BCE with target 0
        accO = (long long)((double)bce0 * SCALE_);
    }
    if (i0 < B_*T_) {                                 // bin target i0
        int b = i0 >> 10;
        int t = i0 & (T_ - 1);
        const float* g = gt + (size_t)i0 * 3;
        float tc = g[0], tx = g[1], ty = g[2];
        int cx = (int)(tx * 0.125f); cx = min(max(cx, 0), G_-1);
        int cy = (int)(ty * 0.125f); cy = min(max(cy, 0), G_-1);
        int cidx = b*NC_ + cy*G_ + cx;
        int pos = atomicAdd(&g_cnt[cidx], 1);
        float4 v = make_float4(tc, tx, ty, __int_as_float(t));
        if (pos < CAP_) {
            g_cell[cidx*CAP_ + pos] = v;
        } else {
            int j = atomicAdd(&g_ovfn[b], 1);
            g_ovf[b*T_ + j] = v;
        }
    }
    accO = wred(accO);
    if (lane == 0 && accO) atomicAdd(&g_acc_obj, (unsigned long long)accO);

    gbar();

    // ---- Phase B: per-pred 3x3 neighborhood scan (single pass) -----------
    if (i0 < B_*P_) {
        int b = i0 >> 12;
        int p = i0 & (P_ - 1);
        float cls = myPred.x, x = myPred.y, y = myPred.z;

        int cx = (int)(x * 0.125f); cx = min(max(cx, 0), G_-1);
        int cy = (int)(y * 0.125f); cy = min(max(cy, 0), G_-1);

        int cidx[9]; int ccnt[9];
        #pragma unroll
        for (int k = 0; k < 9; k++) {                 // front-batched count loads (MLP=9)
            int yy = cy + (k / 3) - 1;
            int xx = cx + (k % 3) - 1;
            bool ok = (yy >= 0) & (yy < G_) & (xx >= 0) & (xx < G_);
            int c = b*NC_ + yy*G_ + xx;
            cidx[k] = c;
            ccnt[k] = ok ? __ldcg(&g_cnt[c]) : 0;
        }

        unsigned long long* bestBase = g_best + b*T_;
        float mind = FLT_MAX;
        #pragma unroll
        for (int k = 0; k < 9; k++) {
            int cnt = min(ccnt[k], CAP_);
            const float4* slot = &g_cell[cidx[k]*CAP_];
            for (int j = 0; j < cnt; j++)
                consider(__ldcg(slot + j), cls, x, y, p, bestBase, mind);
        }
        int novf = __ldcg(&g_ovfn[b]);                // normally 0
        for (int j = 0; j < novf; j++)
            consider(__ldcg(&g_ovf[b*T_ + j]), cls, x, y, p, bestBase, mind);

        g_mind[i0] = mind;
    }

    unsigned long long epoch = gbar();                // launch-unique, > 0

    // ---- Phase C: exactly-once corrections + cleanup + finalize ----------
    long long accCO = 0, accCR = 0;
    if (i0 < B_*P_) g_cnt[i0] = 0;                    // B_*NC_ == B_*P_
    if (i0 < B_)    g_ovfn[i0] = 0;
    if (i0 < B_*T_) {
        unsigned long long v = __ldcg(&g_best[i0]);
        g_best[i0] = 0;                               // reset for next launch
        if (v) {
            unsigned long long vi = ~v;
            int p  = (int)(vi & 0xFFFFFFFFull);
            int b  = i0 >> 10;
            int pi = b*P_ + p;
            // Issue data loads before (independent of) the claim atomic.
            float conf = __ldg(&pred[4*pi + 3]);
            float dmin = __ldcg(&g_mind[pi]);
            if (atomicExch(&g_claim[pi], epoch) != epoch) {   // exactly-once owner
                float d = sqrtf(dmin + 1e-12f);
                float s = 1.0f / (1.0f + expf(-(RADIUS_ - d)));
                accCO = (long long)((double)conf * SCALE_);
                accCR = (long long)((double)s    * SCALE_);
            }
        }
    }
    accCO = wred(accCO);
    accCR = wred(accCR);
    if (lane == 0) {
        if (accCO) atomicAdd(&g_acc_cobj, (unsigned long long)accCO);
        if (accCR) atomicAdd(&g_acc_creg, (unsigned long long)accCR);
    }

    // Last-block finalization (no grid barrier needed)
    __syncthreads();
    if (tid == 0) {
        __threadfence();
        unsigned int t = atomicAdd(&g_done, 1u);
        if ((t % NB_) == (NB_ - 1u)) {
            long long o  = (long long)atomicAdd(&g_acc_obj,  0ull);
            long long co = (long long)atomicAdd(&g_acc_cobj, 0ull);
            long long cr = (long long)atomicAdd(&g_acc_creg, 0ull);
            double inv = 1.0 / (SCALE_ * 65536.0);
            out[0] = (float)(((double)o - (double)co) * inv);   // obj_loss
            out[1] = (float)(1.0 - (double)cr * inv);           // reg_loss
            atomicExch(&g_acc_obj,  0ull);                      // reset for next replay
            atomicExch(&g_acc_cobj, 0ull);
            atomicExch(&g_acc_creg, 0ull);
        }
    }
}

extern "C" void kernel_launch(void* const* d_in, const int* in_sizes, int n_in,
                              void* d_out, int out_size) {
    const float* pred = (const float*)d_in[0];
    const float* gt   = (const float*)d_in[1];
    if (n_in >= 2 && in_sizes[0] == B_*T_*3) {   // defensive input-order check
        const float* tmp = pred; pred = gt; gt = tmp;
    }
    (void)out_size;
    fused_kernel<<<NB_, NT_>>>(pred, gt, (float*)d_out);
}

// round 6
// speedup vs baseline: 2.2144x; 1.2789x over previous
#include <cuda_runtime.h>
#include <float.h>

// Problem constants
#define B_   16
#define P_   4096
#define T_   1024
#define G_   64                 // 64x64 cells of size 8.0 covering [0,512)
#define NC_  (G_*G_)
#define CAP_ 16
#define RADIUS_ 2.5f

#define NB_   256               // 2 blocks/SM on 148 SMs (cap 296) -> co-resident -> barrier safe
#define NT_   256
#define NTOT_ (NB_*NT_)         // 65536 == B_*P_ : exactly one work item per thread

#define SCALE_ 17179869184.0    // 2^34 fixed-point scale (sums < 2^53, exact in int64)

// Scratch (device globals; statically zero-initialized at module load).
// Invariant: every launch leaves all state "empty" for the next replay.
__device__ int                g_cnt [B_*NC_];       // cleared in phase C
__device__ float4             g_cell[B_*NC_*CAP_];  // guarded by g_cnt
__device__ int                g_ovfn[B_];           // cleared in phase C
__device__ float4             g_ovf [B_*T_];        // guarded by g_ovfn
__device__ unsigned long long g_best[B_*T_];   // atomicMax of ~((dsq<<32)|p); 0=empty; cleared in C
__device__ float              g_mind[B_*P_];   // fully overwritten each launch in phase B
__device__ unsigned long long g_claim[B_*P_];  // epoch tags; monotonic, never cleared
__device__ unsigned long long g_acc_obj;       // fixed-point Σ bce_base        (reset by last block)
__device__ unsigned long long g_acc_cobj;      // fixed-point Σ_{correct} conf  (reset by last block)
__device__ unsigned long long g_acc_creg;      // fixed-point Σ_{correct} sigm  (reset by last block)
__device__ unsigned long long g_bar;           // monotonic ticket barrier
__device__ unsigned int       g_done;          // monotonic last-block counter

// Grid barrier; returns the (launch-unique, monotonic) release ticket.
__device__ __forceinline__ unsigned long long gbar() {
    __shared__ unsigned long long sh_tgt;
    __syncthreads();
    if (threadIdx.x == 0) {
        __threadfence();
        unsigned long long my  = atomicAdd(&g_bar, 1ull);
        unsigned long long tgt = (my / NB_ + 1ull) * NB_;
        while (*((volatile unsigned long long*)&g_bar) < tgt) __nanosleep(32);
        sh_tgt = tgt;
    }
    __syncthreads();
    return sh_tgt;
}

__device__ __forceinline__ long long wred(long long v) {
    #pragma unroll
    for (int o = 16; o; o >>= 1) v += __shfl_down_sync(0xFFFFFFFFu, v, o);
    return v;
}

__device__ __forceinline__ void consider(float4 v, float cls, float x, float y,
                                         int p, unsigned long long* bestBase,
                                         float& mind) {
    float dx = x - v.y, dy = y - v.z;
    float dsq = dx*dx + dy*dy;
    mind = fminf(mind, dsq);
    float d = sqrtf(dsq + 1e-12f);
    if (d <= RADIUS_ && cls == v.x) {
        int t = __float_as_int(v.w);
        // min over (dsq, p) lexicographic == max over bitwise-NOT; 0 stays "empty"
        unsigned long long key = ~(((unsigned long long)__float_as_uint(dsq) << 32)
                                   | (unsigned int)p);
        atomicMax(bestBase + t, key);
    }
}

__global__ void __launch_bounds__(NT_, 2)
fused_kernel(const float* __restrict__ pred, const float* __restrict__ gt,
             float* __restrict__ out) {
    const int tid  = threadIdx.x;
    const int i0   = blockIdx.x * NT_ + tid;   // in [0, 65536) == one pred each
    const int lane = tid & 31;
    const float4* __restrict__ pred4 = reinterpret_cast<const float4*>(pred);

    // ---- Phase A: bin targets + base obj sum (single pass) ---------------
    float4 myPred = __ldg(pred4 + i0);                // {cls,x,y,conf} — reused in phase B
    {
        float c = myPred.w;
        float bce0 = fmaxf(c, 0.0f) + log1pf(expf(-fabsf(c)));  // BCE with target 0
        long long accO = (long long)((double)bce0 * SCALE_);
        accO = wred(accO);
        if (lane == 0) atomicAdd(&g_acc_obj, (unsigned long long)accO);
    }
    if (i0 < B_*T_) {                                 // bin target i0
        int b = i0 >> 10;
        int t = i0 & (T_ - 1);
        const float* g = gt + (size_t)i0 * 3;
        float tc = g[0], tx = g[1], ty = g[2];
        int cx = (int)(tx * 0.125f); cx = min(max(cx, 0), G_-1);
        int cy = (int)(ty * 0.125f); cy = min(max(cy, 0), G_-1);
        int cidx = b*NC_ + cy*G_ + cx;
        int pos = atomicAdd(&g_cnt[cidx], 1);
        float4 v = make_float4(tc, tx, ty, __int_as_float(t));
        if (pos < CAP_) {
            g_cell[cidx*CAP_ + pos] = v;
        } else {
            int j = atomicAdd(&g_ovfn[b], 1);
            g_ovf[b*T_ + j] = v;
        }
    }

    gbar();

    // ---- Phase B: per-pred 2x2 neighborhood scan (disk radius 2.5 < cell/2=4,
    //       so the 2.5-disk intersects at most 2 cells per axis) ------------
    {
        int b = i0 >> 12;
        int p = i0 & (P_ - 1);
        float cls = myPred.x, x = myPred.y, y = myPred.z;

        int cx = (int)(x * 0.125f); cx = min(max(cx, 0), G_-1);
        int cy = (int)(y * 0.125f); cy = min(max(cy, 0), G_-1);
        float fx = x - (float)cx * 8.0f;
        float fy = y - (float)cy * 8.0f;
        int nx = cx + ((fx <= RADIUS_) ? -1 : ((fx >= 8.0f - RADIUS_) ? 1 : 0));
        int ny = cy + ((fy <= RADIUS_) ? -1 : ((fy >= 8.0f - RADIUS_) ? 1 : 0));
        bool vx = (nx != cx) & (nx >= 0) & (nx < G_);
        bool vy = (ny != cy) & (ny >= 0) & (ny < G_);

        // 4 candidate cells; invalid ones clamp to cell 0 of this batch (in-bounds)
        // and get cnt forced to 0.
        int  cell[4];
        bool ok[4];
        cell[0] = b*NC_ + cy*G_ + cx;              ok[0] = true;
        cell[1] = vx ? (b*NC_ + cy*G_ + nx) : b*NC_;  ok[1] = vx;
        cell[2] = vy ? (b*NC_ + ny*G_ + cx) : b*NC_;  ok[2] = vy;
        cell[3] = (vx & vy) ? (b*NC_ + ny*G_ + nx) : b*NC_;  ok[3] = vx & vy;

        // Front-batch: 4 counts + 4 speculative slot-0 loads, all independent.
        int    ccnt[4];
        float4 s0[4];
        #pragma unroll
        for (int k = 0; k < 4; k++) {
            ccnt[k] = ok[k] ? __ldcg(&g_cnt[cell[k]]) : 0;
            s0[k]   = __ldcg(&g_cell[cell[k]*CAP_]);   // masked by ccnt below
        }

        unsigned long long* bestBase = g_best + b*T_;
        float mind = FLT_MAX;
        #pragma unroll
        for (int k = 0; k < 4; k++) {
            int cnt = min(ccnt[k], CAP_);
            if (cnt > 0) consider(s0[k], cls, x, y, p, bestBase, mind);
            const float4* slot = &g_cell[cell[k]*CAP_];
            for (int j = 1; j < cnt; j++)              // rare (P ~ 2.6%)
                consider(__ldcg(slot + j), cls, x, y, p, bestBase, mind);
        }
        int novf = __ldcg(&g_ovfn[b]);                 // normally 0
        for (int j = 0; j < novf; j++)
            consider(__ldcg(&g_ovf[b*T_ + j]), cls, x, y, p, bestBase, mind);

        g_mind[i0] = mind;
    }

    unsigned long long epoch = gbar();                 // launch-unique, > 0

    // ---- Phase C: exactly-once corrections + cleanup + finalize ----------
    long long accCO = 0, accCR = 0;
    g_cnt[i0] = 0;                                     // B_*NC_ == B_*P_
    if (i0 < B_) g_ovfn[i0] = 0;
    if (i0 < B_*T_) {
        unsigned long long v = __ldcg(&g_best[i0]);
        g_best[i0] = 0;                                // reset for next launch
        if (v) {
            unsigned long long vi = ~v;
            int p  = (int)(vi & 0xFFFFFFFFull);
            int b  = i0 >> 10;
            int pi = b*P_ + p;
            // Issue data loads before (independent of) the claim atomic.
            float conf = __ldg(&pred[4*pi + 3]);
            float dmin = __ldcg(&g_mind[pi]);
            if (atomicExch(&g_claim[pi], epoch) != epoch) {   // exactly-once owner
                float d = sqrtf(dmin + 1e-12f);
                float s = 1.0f / (1.0f + expf(-(RADIUS_ - d)));
                accCO = (long long)((double)conf * SCALE_);
                accCR = (long long)((double)s    * SCALE_);
            }
        }
    }
    accCO = wred(accCO);
    accCR = wred(accCR);
    if (lane == 0) {
        if (accCO) atomicAdd(&g_acc_cobj, (unsigned long long)accCO);
        if (accCR) atomicAdd(&g_acc_creg, (unsigned long long)accCR);
    }

    // Last-block finalization (no grid barrier needed)
    __syncthreads();
    if (tid == 0) {
        __threadfence();
        unsigned int t = atomicAdd(&g_done, 1u);
        if ((t % NB_) == (NB_ - 1u)) {
            long long o  = (long long)atomicAdd(&g_acc_obj,  0ull);
            long long co = (long long)atomicAdd(&g_acc_cobj, 0ull);
            long long cr = (long long)atomicAdd(&g_acc_creg, 0ull);
            double inv = 1.0 / (SCALE_ * 65536.0);
            out[0] = (float)(((double)o - (double)co) * inv);   // obj_loss
            out[1] = (float)(1.0 - (double)cr * inv);           // reg_loss
            atomicExch(&g_acc_obj,  0ull);                      // reset for next replay
            atomicExch(&g_acc_cobj, 0ull);
            atomicExch(&g_acc_creg, 0ull);
        }
    }
}

extern "C" void kernel_launch(void* const* d_in, const int* in_sizes, int n_in,
                              void* d_out, int out_size) {
    const float* pred = (const float*)d_in[0];
    const float* gt   = (const float*)d_in[1];
    if (n_in >= 2 && in_sizes[0] == B_*T_*3) {   // defensive input-order check
        const float* tmp = pred; pred = gt; gt = tmp;
    }
    (void)out_size;
    fused_kernel<<<NB_, NT_>>>(pred, gt, (float*)d_out);
}